// round 9
// baseline (speedup 1.0000x reference)
#include <cuda_runtime.h>
#include <math.h>

#define NBLOCKS  888             // 148 SMs * 6 blocks (regs ~40 -> 6 CTAs/SM)
#define NTHREADS 256
#define UNROLL   4               // 4 x 256-bit loads = 128 B per thread per iter

__device__ float        g_partials[NBLOCKS];
__device__ unsigned int g_ticket = 0;

__device__ __forceinline__ float rsqrt_approx(float x) {
    float r;
    asm("rsqrt.approx.f32 %0, %1;" : "=f"(r) : "f"(x));
    return r;
}

// 256-bit streaming global load (sm_100+: LDG.E.256)
__device__ __forceinline__ void ldg256_cs(const float* __restrict__ p, float* r) {
    asm("ld.global.cs.v8.f32 {%0,%1,%2,%3,%4,%5,%6,%7}, [%8];"
        : "=f"(r[0]), "=f"(r[1]), "=f"(r[2]), "=f"(r[3]),
          "=f"(r[4]), "=f"(r[5]), "=f"(r[6]), "=f"(r[7])
        : "l"(p));
}

__device__ __forceinline__ float sq8(const float* f) {
    float s = f[0] * f[0] + f[1] * f[1] + f[2] * f[2] + f[3] * f[3];
    s      += f[4] * f[4] + f[5] * f[5] + f[6] * f[6] + f[7] * f[7];
    return s;
}

// One float8 = half a row (D=16). Lane pairs (2j, 2j+1) own a row: combine the
// two halves, return this lane's share of (|row|-1)^2 (0.5x in each lane).
__device__ __forceinline__ float pair_loss(float s, bool active) {
    s += __shfl_xor_sync(0xFFFFFFFFu, s, 1);
    float r = s * rsqrt_approx(s) - 1.0f;   // sqrt(s) - 1, one MUFU.RSQ
    return active ? 0.5f * r * r : 0.0f;
}

__global__ void __launch_bounds__(NTHREADS)
loss_kernel(const float* __restrict__ y, long long nvec8,
            float* __restrict__ out, float inv_scale) {
    const long long tid = (long long)blockIdx.x * NTHREADS + threadIdx.x;
    const long long T   = (long long)NBLOCKS * NTHREADS;   // multiple of 2

    const long long kfull = nvec8 / (UNROLL * T);   // uniform trip count

    float acc = 0.0f;
    for (long long k = 0; k < kfull; k++) {
        long long v = tid + k * (UNROLL * T);      // float8 index
        float f[UNROLL][8];
        #pragma unroll
        for (int u = 0; u < UNROLL; u++)           // 4 front-batched LDG.256
            ldg256_cs(y + (v + (long long)u * T) * 8, f[u]);
        #pragma unroll
        for (int u = 0; u < UNROLL; u++)
            acc += pair_loss(sq8(f[u]), true);
    }

    // Predicated tail (active cutoff is even -> lane-pair uniform)
    {
        long long base = kfull * (UNROLL * T);
        #pragma unroll
        for (int t = 0; t < UNROLL; t++) {
            long long v = base + (long long)t * T + tid;
            bool active = v < nvec8;
            float s = 0.0f;
            if (active) {
                float f[8];
                ldg256_cs(y + v * 8, f);
                s = sq8(f);
            }
            acc += pair_loss(s, active);
        }
    }

    // block reduction
    #pragma unroll
    for (int m = 16; m > 0; m >>= 1)
        acc += __shfl_xor_sync(0xFFFFFFFFu, acc, m);

    __shared__ float warp_sums[NTHREADS / 32];
    int wid = threadIdx.x >> 5;
    int lid = threadIdx.x & 31;
    if (lid == 0) warp_sums[wid] = acc;
    __syncthreads();

    if (wid == 0) {
        float b = (lid < NTHREADS / 32) ? warp_sums[lid] : 0.0f;
        #pragma unroll
        for (int m = 4; m > 0; m >>= 1)
            b += __shfl_xor_sync(0xFFFFFFFFu, b, m);
        if (lid == 0)
            g_partials[blockIdx.x] = b;
    }

    // single-kernel fan-in: last block reduces the partials
    __shared__ bool is_last;
    __threadfence();
    if (threadIdx.x == 0) {
        unsigned int old = atomicAdd(&g_ticket, 1u);
        is_last = (old == (unsigned)gridDim.x - 1u);
    }
    __syncthreads();

    if (is_last) {
        float s = 0.0f;
        for (int i = threadIdx.x; i < (int)gridDim.x; i += NTHREADS)
            s += g_partials[i];
        #pragma unroll
        for (int m = 16; m > 0; m >>= 1)
            s += __shfl_xor_sync(0xFFFFFFFFu, s, m);
        if (lid == 0) warp_sums[wid] = s;
        __syncthreads();
        if (wid == 0) {
            float b = (lid < NTHREADS / 32) ? warp_sums[lid] : 0.0f;
            #pragma unroll
            for (int m = 4; m > 0; m >>= 1)
                b += __shfl_xor_sync(0xFFFFFFFFu, b, m);
            if (lid == 0) {
                out[0]   = b * inv_scale;   // LAMBDA1 = 1.0
                g_ticket = 0;               // reset for next graph replay
            }
        }
    }
}

extern "C" void kernel_launch(void* const* d_in, const int* in_sizes, int n_in,
                              void* d_out, int out_size) {
    const float* y    = (const float*)d_in[0];
    long long n_elems = (long long)in_sizes[0];   // N * D
    long long nvec8   = n_elems / 8;
    float inv_scale   = (float)(1.0 / (double)n_elems);

    loss_kernel<<<NBLOCKS, NTHREADS>>>(y, nvec8, (float*)d_out, inv_scale);
}

// round 10
// speedup vs baseline: 1.0768x; 1.0768x over previous
#include <cuda_runtime.h>
#include <math.h>

#define NBLOCKS  1036            // 148 SMs * 7 blocks (32-bit indexing -> regs <= 35)
#define NTHREADS 256
#define UNROLL   8

__device__ float        g_partials[NBLOCKS];
__device__ unsigned int g_ticket = 0;

__device__ __forceinline__ float rsqrt_approx(float x) {
    float r;
    asm("rsqrt.approx.f32 %0, %1;" : "=f"(r) : "f"(x));
    return r;
}

// lanes 4j..4j+3 hold the 4 segments of one row; combine, then return this
// lane's share of (|row|-1)^2 (0.25x in each of the 4 lanes).
__device__ __forceinline__ float quad_loss(float s, bool active) {
    s += __shfl_xor_sync(0xFFFFFFFFu, s, 1);
    s += __shfl_xor_sync(0xFFFFFFFFu, s, 2);
    float r = s * rsqrt_approx(s) - 1.0f;   // sqrt(s) - 1, one MUFU.RSQ
    return active ? 0.25f * r * r : 0.0f;
}

__device__ __forceinline__ float sq4(float4 f) {
    return f.x * f.x + f.y * f.y + f.z * f.z + f.w * f.w;
}

__global__ void __launch_bounds__(NTHREADS)
loss_kernel(const float4* __restrict__ y4, unsigned int nvec,
            float* __restrict__ out, float inv_scale) {
    const unsigned int tid = blockIdx.x * NTHREADS + threadIdx.x;
    const unsigned int T   = NBLOCKS * NTHREADS;        // multiple of 4

    const unsigned int kfull = nvec / (UNROLL * T);     // uniform trip count

    float acc = 0.0f;
    for (unsigned int k = 0; k < kfull; k++) {
        unsigned int v = tid + k * (UNROLL * T);
        float4 f[UNROLL];
        #pragma unroll
        for (int u = 0; u < UNROLL; u++)                // 8 front-batched LDG.128
            f[u] = __ldcs(&y4[v + (unsigned)u * T]);
        #pragma unroll
        for (int u = 0; u < UNROLL; u++)
            acc += quad_loss(sq4(f[u]), true);
    }

    // Predicated uniform tail (nvec % 4 == 0 -> quad-uniform activity)
    {
        unsigned int base = kfull * (UNROLL * T);
        #pragma unroll
        for (int t = 0; t < UNROLL; t++) {
            unsigned int v = base + (unsigned)t * T + tid;
            bool active = v < nvec;
            float s = active ? sq4(__ldcs(&y4[v])) : 0.0f;
            acc += quad_loss(s, active);
        }
    }

    // block reduction
    #pragma unroll
    for (int m = 16; m > 0; m >>= 1)
        acc += __shfl_xor_sync(0xFFFFFFFFu, acc, m);

    __shared__ float warp_sums[NTHREADS / 32];
    int wid = threadIdx.x >> 5;
    int lid = threadIdx.x & 31;
    if (lid == 0) warp_sums[wid] = acc;
    __syncthreads();

    if (wid == 0) {
        float b = (lid < NTHREADS / 32) ? warp_sums[lid] : 0.0f;
        #pragma unroll
        for (int m = 4; m > 0; m >>= 1)
            b += __shfl_xor_sync(0xFFFFFFFFu, b, m);
        if (lid == 0)
            g_partials[blockIdx.x] = b;
    }

    // single-kernel fan-in: last block reduces the partials
    __shared__ bool is_last;
    __threadfence();
    if (threadIdx.x == 0) {
        unsigned int old = atomicAdd(&g_ticket, 1u);
        is_last = (old == (unsigned)gridDim.x - 1u);
    }
    __syncthreads();

    if (is_last) {
        float s = 0.0f;
        for (int i = threadIdx.x; i < (int)gridDim.x; i += NTHREADS)
            s += g_partials[i];
        #pragma unroll
        for (int m = 16; m > 0; m >>= 1)
            s += __shfl_xor_sync(0xFFFFFFFFu, s, m);
        if (lid == 0) warp_sums[wid] = s;
        __syncthreads();
        if (wid == 0) {
            float b = (lid < NTHREADS / 32) ? warp_sums[lid] : 0.0f;
            #pragma unroll
            for (int m = 4; m > 0; m >>= 1)
                b += __shfl_xor_sync(0xFFFFFFFFu, b, m);
            if (lid == 0) {
                out[0]   = b * inv_scale;   // LAMBDA1 = 1.0
                g_ticket = 0;               // reset for next graph replay
            }
        }
    }
}

extern "C" void kernel_launch(void* const* d_in, const int* in_sizes, int n_in,
                              void* d_out, int out_size) {
    const float4* y4   = (const float4*)d_in[0];
    unsigned int nvec  = (unsigned int)(in_sizes[0] / 4);   // N*D/4 float4s
    float inv_scale    = (float)(1.0 / (double)in_sizes[0]);

    loss_kernel<<<NBLOCKS, NTHREADS>>>(y4, nvec, (float*)d_out, inv_scale);
}